// round 2
// baseline (speedup 1.0000x reference)
#include <cuda_runtime.h>
#include <cuda_bf16.h>
#include <stdint.h>

typedef __nv_bfloat16 bf16;

// ---------------- static device scratch (no runtime allocation) -------------
__device__ bf16 d_embB[(size_t)50000 * 304];        // padded bf16 embedding
__device__ bf16 d_WxB[304 * 2048];                  // padded bf16 Wx
__device__ bf16 d_WhB[512 * 2048];
__device__ bf16 d_W1B[512 * 1024];
__device__ bf16 d_W2B[1024 * 1024];
__device__ bf16 d_xg[(size_t)32768 * 2048];         // time-major [t][b][g]
__device__ bf16 d_h[2][64 * 512];                   // ping-pong h
__device__ bf16 d_a1[64 * 1024];
__device__ bf16 d_a2[64 * 1024];
__device__ unsigned int d_bar;

// ---------------- helpers ---------------------------------------------------
__device__ __forceinline__ uint32_t pack_bf2(float a, float b) {
    __nv_bfloat162 t = __floats2bfloat162_rn(a, b);
    return *reinterpret_cast<uint32_t*>(&t);
}

__device__ __forceinline__ void mma16816(float* c, const uint32_t* a, const uint32_t* b) {
    asm volatile(
        "mma.sync.aligned.m16n8k16.row.col.f32.bf16.bf16.f32 "
        "{%0,%1,%2,%3},{%4,%5,%6,%7},{%8,%9},{%0,%1,%2,%3};"
        : "+f"(c[0]), "+f"(c[1]), "+f"(c[2]), "+f"(c[3])
        : "r"(a[0]), "r"(a[1]), "r"(a[2]), "r"(a[3]), "r"(b[0]), "r"(b[1]));
}

// ---------------- init / conversion -----------------------------------------
__global__ void k_zero() {
    int i = blockIdx.x * 1024 + threadIdx.x;
    d_h[0][i] = __float2bfloat16(0.f);
    if (i == 0) d_bar = 0u;
}

__global__ void k_cvt_emb(const float* __restrict__ e) {
    long long i = (long long)blockIdx.x * 256 + threadIdx.x;
    if (i >= 50000LL * 304) return;
    int r = (int)(i / 304), c = (int)(i % 304);
    d_embB[i] = __float2bfloat16(c < 300 ? e[(size_t)r * 300 + c] : 0.f);
}

__global__ void k_cvt_wx(const float* __restrict__ Wx) {
    int i = blockIdx.x * 256 + threadIdx.x;
    if (i >= 304 * 2048) return;
    int r = i >> 11;
    d_WxB[i] = __float2bfloat16(r < 300 ? Wx[i] : 0.f);
}

__global__ void k_cvt3(const float* __restrict__ Wh, const float* __restrict__ W1,
                       const float* __restrict__ W2) {
    int i = blockIdx.x * 256 + threadIdx.x;
    if (i < 1048576)       d_WhB[i]           = __float2bfloat16(Wh[i]);
    else if (i < 1572864)  d_W1B[i - 1048576] = __float2bfloat16(W1[i - 1048576]);
    else if (i < 2621440)  d_W2B[i - 1572864] = __float2bfloat16(W2[i - 1572864]);
}

// ---------------- Phase A: xg = gather(emb)@Wx + b  (time-major bf16) -------
__global__ void __launch_bounds__(256) k_phaseA(const int* __restrict__ tokens,
                                                const float* __restrict__ bias) {
    __shared__ bf16 As[128 * 24];   // 128 rows x 16 k (pitch 24)
    __shared__ bf16 Bs[128 * 24];   // 128 n    x 16 k (pitch 24)
    __shared__ int stok[128];

    int tid = threadIdx.x;
    int n0 = blockIdx.x * 128;
    int m0 = blockIdx.y * 128;
    if (tid < 128) stok[tid] = tokens[m0 + tid];
    __syncthreads();

    int w = tid >> 5, lane = tid & 31, g = lane >> 2, tq = lane & 3;
    int wm = (w >> 2) * 64;   // 2 warp-rows x 64
    int wn = (w & 3) * 32;    // 4 warp-cols x 32

    float C[4][4][4];
    #pragma unroll
    for (int a = 0; a < 4; a++)
        #pragma unroll
        for (int b2 = 0; b2 < 4; b2++)
            #pragma unroll
            for (int c = 0; c < 4; c++) C[a][b2][c] = 0.f;

    for (int ks = 0; ks < 19; ks++) {
        int k0 = ks * 16;
        // A tile: gather 128 rows x 16 k from padded bf16 table
        #pragma unroll
        for (int r = 0; r < 2; r++) {
            int idx = tid + r * 256;
            int row = idx >> 2, q = idx & 3;
            uint2 v = *reinterpret_cast<const uint2*>(
                &d_embB[(size_t)stok[row] * 304 + k0 + q * 4]);
            *reinterpret_cast<uint2*>(&As[row * 24 + q * 4]) = v;
        }
        // B tile: 16 k-rows x 128 n, transpose into Bs[n][k]
        {
            int krow = tid >> 4, c8 = tid & 15;
            uint4 v = *reinterpret_cast<const uint4*>(
                &d_WxB[(size_t)(k0 + krow) * 2048 + n0 + c8 * 8]);
            const bf16* e = reinterpret_cast<const bf16*>(&v);
            #pragma unroll
            for (int j = 0; j < 8; j++) Bs[(c8 * 8 + j) * 24 + krow] = e[j];
        }
        __syncthreads();

        uint32_t Bf[4][2];
        #pragma unroll
        for (int no = 0; no < 4; no++) {
            int n = wn + no * 8 + g;
            Bf[no][0] = *reinterpret_cast<const uint32_t*>(&Bs[n * 24 + 2 * tq]);
            Bf[no][1] = *reinterpret_cast<const uint32_t*>(&Bs[n * 24 + 2 * tq + 8]);
        }
        #pragma unroll
        for (int mo = 0; mo < 4; mo++) {
            int r = wm + mo * 16;
            uint32_t Af[4];
            Af[0] = *reinterpret_cast<const uint32_t*>(&As[(r + g) * 24 + 2 * tq]);
            Af[1] = *reinterpret_cast<const uint32_t*>(&As[(r + g + 8) * 24 + 2 * tq]);
            Af[2] = *reinterpret_cast<const uint32_t*>(&As[(r + g) * 24 + 2 * tq + 8]);
            Af[3] = *reinterpret_cast<const uint32_t*>(&As[(r + g + 8) * 24 + 2 * tq + 8]);
            #pragma unroll
            for (int no = 0; no < 4; no++) mma16816(C[mo][no], Af, Bf[no]);
        }
        __syncthreads();
    }

    // epilogue: +bias, bf16, scatter to time-major xg
    #pragma unroll
    for (int mo = 0; mo < 4; mo++) {
        #pragma unroll
        for (int no = 0; no < 4; no++) {
            int gcol = n0 + wn + no * 8 + 2 * tq;
            float b0 = bias[gcol], b1v = bias[gcol + 1];
            int m1 = m0 + wm + mo * 16 + g;
            int m2 = m1 + 8;
            size_t o1 = ((size_t)((m1 & 511) * 64 + (m1 >> 9))) * 2048 + gcol;
            size_t o2 = ((size_t)((m2 & 511) * 64 + (m2 >> 9))) * 2048 + gcol;
            *reinterpret_cast<uint32_t*>(&d_xg[o1]) =
                pack_bf2(C[mo][no][0] + b0, C[mo][no][1] + b1v);
            *reinterpret_cast<uint32_t*>(&d_xg[o2]) =
                pack_bf2(C[mo][no][2] + b0, C[mo][no][3] + b1v);
        }
    }
}

// ---------------- Recurrence: 16 persistent CTAs, 512 steps -----------------
// SMEM layout: Ws 128x520 bf16 (133120 B) | hs 64x520 bf16 (66560 B) |
//              gb 64x132 bf16 (16896 B)  -> total 216576 B
__global__ void __launch_bounds__(512, 1) k_recur(const int* __restrict__ tokens) {
    extern __shared__ char sm_raw[];
    bf16* Ws = reinterpret_cast<bf16*>(sm_raw);
    bf16* hs = reinterpret_cast<bf16*>(sm_raw + 133120);
    bf16* gb = reinterpret_cast<bf16*>(sm_raw + 199680);

    int tid = threadIdx.x, cta = blockIdx.x;
    int u0 = cta * 32;

    // load this CTA's gate-reordered Wh slice: n in [0,128): gate=n>>5, unit=u0+(n&31)
    for (int i = tid; i < 128 * 512; i += 512) {
        int n = i & 127, k = i >> 7;
        int gcol = (n >> 5) * 512 + u0 + (n & 31);
        Ws[n * 520 + k] = d_WhB[k * 2048 + gcol];
    }

    int w = tid >> 5, lane = tid & 31, g = lane >> 2, tq = lane & 3;
    int wm = (w >> 2) * 16;   // 4 m-groups x 16
    int wn = (w & 3) * 32;    // 4 n-groups x 32
    float cst[4] = {0.f, 0.f, 0.f, 0.f};
    int e_un = tid & 31;
    int e_r0 = tid >> 5;      // epilogue rows e_r0 + 16*j
    __syncthreads();

    for (int t = 0; t < 512; t++) {
        const bf16* hsrc = d_h[t & 1];
        for (int i = tid; i < 4096; i += 512) {      // 64x512 bf16 via uint4
            int row = i >> 6, qc = i & 63;
            *reinterpret_cast<uint4*>(&hs[row * 520 + qc * 8]) =
                __ldcg(reinterpret_cast<const uint4*>(&hsrc[row * 512 + qc * 8]));
        }
        __syncthreads();

        float C[4][4];
        #pragma unroll
        for (int a = 0; a < 4; a++) { C[a][0] = C[a][1] = C[a][2] = C[a][3] = 0.f; }
        #pragma unroll 4
        for (int ks = 0; ks < 32; ks++) {
            int k0 = ks * 16;
            uint32_t A[4];
            A[0] = *reinterpret_cast<const uint32_t*>(&hs[(wm + g) * 520 + k0 + 2 * tq]);
            A[1] = *reinterpret_cast<const uint32_t*>(&hs[(wm + g + 8) * 520 + k0 + 2 * tq]);
            A[2] = *reinterpret_cast<const uint32_t*>(&hs[(wm + g) * 520 + k0 + 2 * tq + 8]);
            A[3] = *reinterpret_cast<const uint32_t*>(&hs[(wm + g + 8) * 520 + k0 + 2 * tq + 8]);
            #pragma unroll
            for (int j = 0; j < 4; j++) {
                uint32_t B[2];
                int n = wn + j * 8 + g;
                B[0] = *reinterpret_cast<const uint32_t*>(&Ws[n * 520 + k0 + 2 * tq]);
                B[1] = *reinterpret_cast<const uint32_t*>(&Ws[n * 520 + k0 + 2 * tq + 8]);
                mma16816(C[j], A, B);
            }
        }
        #pragma unroll
        for (int j = 0; j < 4; j++) {
            int col = wn + j * 8 + 2 * tq;
            *reinterpret_cast<uint32_t*>(&gb[(wm + g) * 132 + col]) =
                pack_bf2(C[j][0], C[j][1]);
            *reinterpret_cast<uint32_t*>(&gb[(wm + g + 8) * 132 + col]) =
                pack_bf2(C[j][2], C[j][3]);
        }
        __syncthreads();

        bf16* hdst = d_h[(t + 1) & 1];
        const bf16* xg = d_xg + (size_t)t * 131072;
        #pragma unroll
        for (int j = 0; j < 4; j++) {
            int r = e_r0 + 16 * j;
            const bf16* xr = xg + r * 2048 + u0 + e_un;
            float gi = __bfloat162float(gb[r * 132 + e_un])      + __bfloat162float(xr[0]);
            float gf = __bfloat162float(gb[r * 132 + 32 + e_un]) + __bfloat162float(xr[512]);
            float gc = __bfloat162float(gb[r * 132 + 64 + e_un]) + __bfloat162float(xr[1024]);
            float go = __bfloat162float(gb[r * 132 + 96 + e_un]) + __bfloat162float(xr[1536]);
            float si = 1.f / (1.f + __expf(-gi));
            float sf = 1.f / (1.f + __expf(-gf));
            float so = 1.f / (1.f + __expf(-go));
            float cn = sf * cst[j] + si * fmaxf(gc, 0.f);
            float hn = so * fmaxf(cn, 0.f);
            float hout;
            if (tokens[r * 512 + t] != 0) { cst[j] = cn; hout = hn; }
            else { hout = __bfloat162float(hs[r * 520 + u0 + e_un]); }
            hdst[r * 512 + u0 + e_un] = __float2bfloat16(hout);
        }
        __syncthreads();   // hs/gb reuse + all stores issued before signaling

        if (t < 511) {
            if (tid == 0) {
                __threadfence();
                atomicAdd(&d_bar, 1u);
                unsigned tgt = 16u * (unsigned)(t + 1);
                while (*(volatile unsigned int*)&d_bar < tgt) { }
                __threadfence();
            }
            __syncthreads();
        }
    }
}

// ---------------- MLP layers -------------------------------------------------
__global__ void __launch_bounds__(256) k_mlp(int mode, const float* __restrict__ bias) {
    const bf16* A; const bf16* W; bf16* out; int K;
    if (mode == 0) { A = d_h[0]; W = d_W1B; out = d_a1; K = 512; }
    else           { A = d_a1;   W = d_W2B; out = d_a2; K = 1024; }
    int tid = threadIdx.x;
    int col = blockIdx.x * 64 + (tid & 63);
    int rb = blockIdx.y * 16 + (tid >> 6);   // rows rb + 4*j
    float acc[4] = {0.f, 0.f, 0.f, 0.f};
    for (int k = 0; k < K; k++) {
        float wv = __bfloat162float(W[k * 1024 + col]);
        #pragma unroll
        for (int j = 0; j < 4; j++)
            acc[j] += __bfloat162float(A[(rb + 4 * j) * K + k]) * wv;
    }
    float bv = bias[col];
    #pragma unroll
    for (int j = 0; j < 4; j++)
        out[(rb + 4 * j) * 1024 + col] = __float2bfloat16(fmaxf(acc[j] + bv, 0.f));
}

// ---------------- logits + softmax ------------------------------------------
__global__ void __launch_bounds__(128) k_out(const float* __restrict__ Wo,
                                             const float* __restrict__ bo,
                                             float* __restrict__ out) {
    __shared__ float red[128 * 20];
    int row = blockIdx.x, tid = threadIdx.x;
    float p[20];
    #pragma unroll
    for (int c = 0; c < 20; c++) p[c] = 0.f;
    for (int k = tid; k < 1024; k += 128) {
        float a = __bfloat162float(d_a2[row * 1024 + k]);
        #pragma unroll
        for (int c = 0; c < 20; c++) p[c] += a * Wo[k * 20 + c];
    }
    #pragma unroll
    for (int c = 0; c < 20; c++) red[tid * 20 + c] = p[c];
    __syncthreads();
    for (int s = 64; s > 0; s >>= 1) {
        if (tid < s) {
            #pragma unroll
            for (int c = 0; c < 20; c++) red[tid * 20 + c] += red[(tid + s) * 20 + c];
        }
        __syncthreads();
    }
    if (tid == 0) {
        float l[20], mx = -1e30f, ss = 0.f;
        #pragma unroll
        for (int c = 0; c < 20; c++) { l[c] = red[c] + bo[c]; mx = fmaxf(mx, l[c]); }
        #pragma unroll
        for (int c = 0; c < 20; c++) { l[c] = __expf(l[c] - mx); ss += l[c]; }
        #pragma unroll
        for (int c = 0; c < 20; c++) out[row * 20 + c] = l[c] / ss;
    }
}

// ---------------- launcher ---------------------------------------------------
extern "C" void kernel_launch(void* const* d_in, const int* in_sizes, int n_in,
                              void* d_out, int out_size) {
    const int*   tokens = (const int*)d_in[0];
    const float* emb = (const float*)d_in[1];
    const float* Wx  = (const float*)d_in[2];
    const float* Wh  = (const float*)d_in[3];
    const float* b   = (const float*)d_in[4];
    const float* W1  = (const float*)d_in[5];
    const float* b1  = (const float*)d_in[6];
    const float* W2  = (const float*)d_in[7];
    const float* b2  = (const float*)d_in[8];
    const float* Wo  = (const float*)d_in[9];
    const float* bo  = (const float*)d_in[10];
    float* out = (float*)d_out;

    cudaFuncSetAttribute(k_recur, cudaFuncAttributeMaxDynamicSharedMemorySize, 216576);

    k_zero<<<32, 1024>>>();
    k_cvt_emb<<<(int)((50000LL * 304 + 255) / 256), 256>>>(emb);
    k_cvt_wx<<<(304 * 2048 + 255) / 256, 256>>>(Wx);
    k_cvt3<<<(2621440 + 255) / 256, 256>>>(Wh, W1, W2);
    k_phaseA<<<dim3(16, 256), 256>>>(tokens, b);
    k_recur<<<16, 512, 216576>>>(tokens);
    k_mlp<<<dim3(16, 4), 256>>>(0, b1);
    k_mlp<<<dim3(16, 4), 256>>>(1, b2);
    k_out<<<64, 128>>>(Wo, bo, out);
}

// round 3
// speedup vs baseline: 1.5430x; 1.5430x over previous
#include <cuda_runtime.h>
#include <cuda_bf16.h>
#include <stdint.h>

typedef __nv_bfloat16 bf16;

// ---------------- static device scratch (no runtime allocation) -------------
__device__ bf16 d_embB[(size_t)50000 * 304];   // padded bf16 embedding [v][304]
__device__ bf16 d_WxT[(size_t)2048 * 304];     // Wx transposed [n][304] bf16
__device__ bf16 d_WhB[512 * 2048];
__device__ bf16 d_W1B[512 * 1024];
__device__ bf16 d_W2B[1024 * 1024];
__device__ bf16 d_xg[(size_t)32768 * 2048];    // time-major [t][b][g]
__device__ bf16 d_h[2][64 * 512];              // ping-pong h
__device__ unsigned char d_maskT[512 * 64];    // [t][b]
__device__ bf16 d_a1[64 * 1024];
__device__ bf16 d_a2[64 * 1024];
__device__ unsigned int d_bar;

// ---------------- helpers ---------------------------------------------------
__device__ __forceinline__ uint32_t pack_bf2(float a, float b) {
    __nv_bfloat162 t = __floats2bfloat162_rn(a, b);
    return *reinterpret_cast<uint32_t*>(&t);
}

__device__ __forceinline__ void mma16816(float* c, const uint32_t* a, const uint32_t* b) {
    asm volatile(
        "mma.sync.aligned.m16n8k16.row.col.f32.bf16.bf16.f32 "
        "{%0,%1,%2,%3},{%4,%5,%6,%7},{%8,%9},{%0,%1,%2,%3};"
        : "+f"(c[0]), "+f"(c[1]), "+f"(c[2]), "+f"(c[3])
        : "r"(a[0]), "r"(a[1]), "r"(a[2]), "r"(a[3]), "r"(b[0]), "r"(b[1]));
}

__device__ __forceinline__ void ldsm4(uint32_t* r, uint32_t addr) {
    asm volatile("ldmatrix.sync.aligned.m8n8.x4.shared.b16 {%0,%1,%2,%3}, [%4];"
                 : "=r"(r[0]), "=r"(r[1]), "=r"(r[2]), "=r"(r[3]) : "r"(addr));
}

__device__ __forceinline__ uint32_t s2u(const void* p) {
    return (uint32_t)__cvta_generic_to_shared(p);
}

// ---------------- init / conversion -----------------------------------------
__global__ void k_zero() {
    int i = blockIdx.x * 1024 + threadIdx.x;
    d_h[0][i] = __float2bfloat16(0.f);
    if (i == 0) d_bar = 0u;
}

__global__ void k_cvt_emb(const float* __restrict__ e) {
    long long i = (long long)blockIdx.x * 256 + threadIdx.x;
    if (i >= 50000LL * 304) return;
    int r = (int)(i / 304), c = (int)(i - 304LL * r);
    d_embB[i] = __float2bfloat16(c < 300 ? e[(size_t)r * 300 + c] : 0.f);
}

__global__ void k_cvt_wxT(const float* __restrict__ Wx) {
    int i = blockIdx.x * 256 + threadIdx.x;
    if (i >= 2048 * 304) return;
    int n = i / 304, k = i - 304 * n;
    d_WxT[i] = __float2bfloat16(k < 300 ? Wx[(size_t)k * 2048 + n] : 0.f);
}

__global__ void k_cvt3(const float* __restrict__ Wh, const float* __restrict__ W1,
                       const float* __restrict__ W2) {
    int i = blockIdx.x * 256 + threadIdx.x;
    if (i < 1048576)       d_WhB[i]           = __float2bfloat16(Wh[i]);
    else if (i < 1572864)  d_W1B[i - 1048576] = __float2bfloat16(W1[i - 1048576]);
    else if (i < 2621440)  d_W2B[i - 1572864] = __float2bfloat16(W2[i - 1572864]);
}

__global__ void k_maskT(const int* __restrict__ tokens) {
    int i = blockIdx.x * 256 + threadIdx.x;   // i < 32768
    int t = i >> 6, b = i & 63;
    d_maskT[i] = (tokens[b * 512 + t] != 0) ? 1 : 0;
}

// ---------------- Phase A: xg = gather(emb)@Wx + b  (time-major bf16) -------
// Whole K=304 resident in SMEM; single load phase, no inner-loop syncs.
__global__ void __launch_bounds__(256) k_phaseA(const int* __restrict__ tokens,
                                                const float* __restrict__ bias) {
    extern __shared__ bf16 smA[];
    bf16* As = smA;                 // 128 x 312
    bf16* Bs = smA + 128 * 312;     // 128 x 312
    __shared__ int stok[128];

    int tid = threadIdx.x;
    int n0 = blockIdx.x * 128;
    int m0 = blockIdx.y * 128;
    if (tid < 128) stok[tid] = tokens[m0 + tid];
    __syncthreads();

    // load: 2 threads per row, 19 uint4 each (304 bf16 per row)
    {
        int row = tid >> 1, half = tid & 1;
        const uint4* sa = reinterpret_cast<const uint4*>(
            &d_embB[(size_t)stok[row] * 304 + half * 152]);
        uint4* da = reinterpret_cast<uint4*>(&As[row * 312 + half * 152]);
        const uint4* sb = reinterpret_cast<const uint4*>(
            &d_WxT[(size_t)(n0 + row) * 304 + half * 152]);
        uint4* db = reinterpret_cast<uint4*>(&Bs[row * 312 + half * 152]);
        #pragma unroll
        for (int j = 0; j < 19; j++) { da[j] = sa[j]; db[j] = sb[j]; }
    }
    __syncthreads();

    int w = tid >> 5, lane = tid & 31, g = lane >> 2, tq = lane & 3;
    int wm = (w >> 2) * 64;   // 2 warp-rows x 64
    int wn = (w & 3) * 32;    // 4 warp-cols x 32
    int lr = lane & 7, lm = lane >> 3;

    // ldmatrix lane base addresses
    uint32_t aab[4], bab[2];
    #pragma unroll
    for (int mo = 0; mo < 4; mo++)
        aab[mo] = s2u(&As[(wm + mo * 16 + lr + (lm & 1) * 8) * 312 + (lm >> 1) * 8]);
    bab[0] = s2u(&Bs[(wn +      lr + (lm >> 1) * 8) * 312 + (lm & 1) * 8]);
    bab[1] = s2u(&Bs[(wn + 16 + lr + (lm >> 1) * 8) * 312 + (lm & 1) * 8]);

    float C[4][4][4];
    #pragma unroll
    for (int a = 0; a < 4; a++)
        #pragma unroll
        for (int b2 = 0; b2 < 4; b2++)
            #pragma unroll
            for (int c = 0; c < 4; c++) C[a][b2][c] = 0.f;

    #pragma unroll 1
    for (int ks = 0; ks < 19; ks++) {
        uint32_t B8[8];
        ldsm4(B8, bab[0] + ks * 32);
        ldsm4(B8 + 4, bab[1] + ks * 32);
        #pragma unroll
        for (int mo = 0; mo < 4; mo++) {
            uint32_t A4[4];
            ldsm4(A4, aab[mo] + ks * 32);
            mma16816(C[mo][0], A4, B8 + 0);
            mma16816(C[mo][1], A4, B8 + 2);
            mma16816(C[mo][2], A4, B8 + 4);
            mma16816(C[mo][3], A4, B8 + 6);
        }
    }

    // epilogue: +bias, bf16, scatter to time-major xg [t][b][g]
    #pragma unroll
    for (int mo = 0; mo < 4; mo++) {
        #pragma unroll
        for (int no = 0; no < 4; no++) {
            int gcol = n0 + wn + no * 8 + 2 * tq;
            float b0 = bias[gcol], b1v = bias[gcol + 1];
            int m1 = m0 + wm + mo * 16 + g;
            int m2 = m1 + 8;
            size_t o1 = ((size_t)((m1 & 511) * 64 + (m1 >> 9))) * 2048 + gcol;
            size_t o2 = ((size_t)((m2 & 511) * 64 + (m2 >> 9))) * 2048 + gcol;
            *reinterpret_cast<uint32_t*>(&d_xg[o1]) =
                pack_bf2(C[mo][no][0] + b0, C[mo][no][1] + b1v);
            *reinterpret_cast<uint32_t*>(&d_xg[o2]) =
                pack_bf2(C[mo][no][2] + b0, C[mo][no][3] + b1v);
        }
    }
}

// ---------------- Recurrence: 64 persistent CTAs x 8 units, 512 steps -------
// dyn SMEM: Ws 32x520 (33280 B) | hs 64x520 (66560 B) | gb 64x36 (4608 B) |
//           ms 64 B  -> total 104512 B
__global__ void __launch_bounds__(256, 1) k_recur() {
    extern __shared__ char smraw[];
    bf16* Ws = reinterpret_cast<bf16*>(smraw);
    bf16* hs = reinterpret_cast<bf16*>(smraw + 33280);
    bf16* gb = reinterpret_cast<bf16*>(smraw + 99840);
    uint32_t* ms4 = reinterpret_cast<uint32_t*>(smraw + 104448);

    int tid = threadIdx.x, cta = blockIdx.x;
    int u0 = cta * 8;

    // Wh slice: col n (0..31) -> gate=(n>>3), unit=u0+(n&7)
    for (int i = tid; i < 32 * 512; i += 256) {
        int n = i & 31, k = i >> 5;
        int gcol = (n >> 3) * 512 + u0 + (n & 7);
        Ws[n * 520 + k] = d_WhB[k * 2048 + gcol];
    }

    int w = tid >> 5, lane = tid & 31, g = lane >> 2, tq = lane & 3;
    int wm = (w & 3) * 16;     // 4 m-tiles x 16
    int wn = (w >> 2) * 16;    // 2 n-tiles x 16
    int lr = lane & 7, lm = lane >> 3;
    uint32_t a_base = s2u(&hs[(wm + lr + (lm & 1) * 8) * 520 + (lm >> 1) * 8]);
    uint32_t b_base = s2u(&Ws[(wn + lr + (lm >> 1) * 8) * 520 + (lm & 1) * 8]);

    int uu = tid & 7, er = tid >> 3;   // epilogue: unit uu, rows er, er+32
    float cst[2] = {0.f, 0.f};
    __syncthreads();

    for (int t = 0; t < 512; t++) {
        const bf16* hsrc = d_h[t & 1];
        for (int i = tid; i < 4096; i += 256) {
            int row = i >> 6, qc = i & 63;
            *reinterpret_cast<uint4*>(&hs[row * 520 + qc * 8]) =
                __ldcg(reinterpret_cast<const uint4*>(&hsrc[row * 512 + qc * 8]));
        }
        if (tid < 16)
            ms4[tid] = *reinterpret_cast<const uint32_t*>(&d_maskT[t * 64 + tid * 4]);
        __syncthreads();

        float C0[4] = {0.f, 0.f, 0.f, 0.f};
        float C1[4] = {0.f, 0.f, 0.f, 0.f};
        #pragma unroll 8
        for (int ks = 0; ks < 32; ks++) {
            uint32_t A4[4], B4[4];
            ldsm4(A4, a_base + ks * 32);
            ldsm4(B4, b_base + ks * 32);
            mma16816(C0, A4, B4);
            mma16816(C1, A4, B4 + 2);
        }
        {
            int col0 = wn + 2 * tq;
            *reinterpret_cast<uint32_t*>(&gb[(wm + g) * 36 + col0])         = pack_bf2(C0[0], C0[1]);
            *reinterpret_cast<uint32_t*>(&gb[(wm + g + 8) * 36 + col0])     = pack_bf2(C0[2], C0[3]);
            *reinterpret_cast<uint32_t*>(&gb[(wm + g) * 36 + col0 + 8])     = pack_bf2(C1[0], C1[1]);
            *reinterpret_cast<uint32_t*>(&gb[(wm + g + 8) * 36 + col0 + 8]) = pack_bf2(C1[2], C1[3]);
        }
        __syncthreads();

        bf16* hdst = d_h[(t + 1) & 1];
        const bf16* xg = d_xg + (size_t)t * 131072;
        #pragma unroll
        for (int it = 0; it < 2; it++) {
            int r = er + it * 32;
            const bf16* xr = xg + r * 2048 + u0 + uu;
            float gi = __bfloat162float(gb[r * 36 + uu])      + __bfloat162float(xr[0]);
            float gf = __bfloat162float(gb[r * 36 + 8 + uu])  + __bfloat162float(xr[512]);
            float gc = __bfloat162float(gb[r * 36 + 16 + uu]) + __bfloat162float(xr[1024]);
            float go = __bfloat162float(gb[r * 36 + 24 + uu]) + __bfloat162float(xr[1536]);
            float si = 1.f / (1.f + __expf(-gi));
            float sf = 1.f / (1.f + __expf(-gf));
            float so = 1.f / (1.f + __expf(-go));
            float cn = sf * cst[it] + si * fmaxf(gc, 0.f);
            float hn = so * fmaxf(cn, 0.f);
            float hout;
            if ((ms4[r >> 2] >> ((r & 3) * 8)) & 0xff) { cst[it] = cn; hout = hn; }
            else { hout = __bfloat162float(hs[r * 520 + u0 + uu]); }
            hdst[r * 512 + u0 + uu] = __float2bfloat16(hout);
        }
        __syncthreads();

        if (t < 511) {
            if (tid == 0) {
                __threadfence();
                atomicAdd(&d_bar, 1u);
                unsigned tgt = 64u * (unsigned)(t + 1);
                while (*(volatile unsigned int*)&d_bar < tgt) { }
                __threadfence();
            }
            __syncthreads();
        }
    }
}

// ---------------- MLP layers -------------------------------------------------
__global__ void __launch_bounds__(256) k_mlp(int mode, const float* __restrict__ bias) {
    const bf16* A; const bf16* W; bf16* out; int K;
    if (mode == 0) { A = d_h[0]; W = d_W1B; out = d_a1; K = 512; }
    else           { A = d_a1;   W = d_W2B; out = d_a2; K = 1024; }
    int tid = threadIdx.x;
    int col = blockIdx.x * 64 + (tid & 63);
    int rb = blockIdx.y * 16 + (tid >> 6);
    float acc[4] = {0.f, 0.f, 0.f, 0.f};
    for (int k = 0; k < K; k++) {
        float wv = __bfloat162float(W[k * 1024 + col]);
        #pragma unroll
        for (int j = 0; j < 4; j++)
            acc[j] += __bfloat162float(A[(rb + 4 * j) * K + k]) * wv;
    }
    float bv = bias[col];
    #pragma unroll
    for (int j = 0; j < 4; j++)
        out[(rb + 4 * j) * 1024 + col] = __float2bfloat16(fmaxf(acc[j] + bv, 0.f));
}

// ---------------- logits + softmax ------------------------------------------
__global__ void __launch_bounds__(128) k_out(const float* __restrict__ Wo,
                                             const float* __restrict__ bo,
                                             float* __restrict__ out) {
    __shared__ float red[128 * 20];
    int row = blockIdx.x, tid = threadIdx.x;
    float p[20];
    #pragma unroll
    for (int c = 0; c < 20; c++) p[c] = 0.f;
    for (int k = tid; k < 1024; k += 128) {
        float a = __bfloat162float(d_a2[row * 1024 + k]);
        #pragma unroll
        for (int c = 0; c < 20; c++) p[c] += a * Wo[k * 20 + c];
    }
    #pragma unroll
    for (int c = 0; c < 20; c++) red[tid * 20 + c] = p[c];
    __syncthreads();
    for (int s = 64; s > 0; s >>= 1) {
        if (tid < s) {
            #pragma unroll
            for (int c = 0; c < 20; c++) red[tid * 20 + c] += red[(tid + s) * 20 + c];
        }
        __syncthreads();
    }
    if (tid == 0) {
        float l[20], mx = -1e30f, ss = 0.f;
        #pragma unroll
        for (int c = 0; c < 20; c++) { l[c] = red[c] + bo[c]; mx = fmaxf(mx, l[c]); }
        #pragma unroll
        for (int c = 0; c < 20; c++) { l[c] = __expf(l[c] - mx); ss += l[c]; }
        #pragma unroll
        for (int c = 0; c < 20; c++) out[row * 20 + c] = l[c] / ss;
    }
}

// ---------------- launcher ---------------------------------------------------
extern "C" void kernel_launch(void* const* d_in, const int* in_sizes, int n_in,
                              void* d_out, int out_size) {
    const int*   tokens = (const int*)d_in[0];
    const float* emb = (const float*)d_in[1];
    const float* Wx  = (const float*)d_in[2];
    const float* Wh  = (const float*)d_in[3];
    const float* b   = (const float*)d_in[4];
    const float* W1  = (const float*)d_in[5];
    const float* b1  = (const float*)d_in[6];
    const float* W2  = (const float*)d_in[7];
    const float* b2  = (const float*)d_in[8];
    const float* Wo  = (const float*)d_in[9];
    const float* bo  = (const float*)d_in[10];
    float* out = (float*)d_out;

    cudaFuncSetAttribute(k_phaseA, cudaFuncAttributeMaxDynamicSharedMemorySize, 159744);
    cudaFuncSetAttribute(k_recur, cudaFuncAttributeMaxDynamicSharedMemorySize, 104512);

    k_zero<<<32, 1024>>>();
    k_cvt_emb<<<(int)((50000LL * 304 + 255) / 256), 256>>>(emb);
    k_cvt_wxT<<<(2048 * 304 + 255) / 256, 256>>>(Wx);
    k_cvt3<<<(2621440 + 255) / 256, 256>>>(Wh, W1, W2);
    k_maskT<<<128, 256>>>(tokens);
    k_phaseA<<<dim3(16, 256), 256, 159744>>>(tokens, b);
    k_recur<<<64, 256, 104512>>>();
    k_mlp<<<dim3(16, 4), 256>>>(0, b1);
    k_mlp<<<dim3(16, 4), 256>>>(1, b2);
    k_out<<<64, 128>>>(Wo, bo, out);
}